// round 3
// baseline (speedup 1.0000x reference)
#include <cuda_runtime.h>
#include <math.h>
#include <stdint.h>

#define CHUNK 128
#define MAXB 32
#define MAXSLOTS 64

// Scratch (no device allocation allowed): per-batch sorted unique chunk list.
__device__ int g_sel[MAXB][MAXSLOTS];
__device__ int g_nsel[MAXB];

// ---------------------------------------------------------------------------
// Kernel 1: build the sorted-unique chunk list per batch.
// order = stable argsort(1 - mask) => selected chunks in ascending id order.
// ---------------------------------------------------------------------------
__global__ void select_kernel(const int* __restrict__ chunk_idx,
                              int B, int sample, int n_chunks) {
    int b = blockIdx.x * blockDim.x + threadIdx.x;
    if (b >= B) return;
    unsigned long long mask = 0ull;
    for (int i = 0; i < sample; ++i) {
        int c = chunk_idx[b * sample + i];
        mask |= (1ull << c);
    }
    int cnt = 0;
    for (int c = 0; c < n_chunks; ++c) {
        if ((mask >> c) & 1ull) {
            g_sel[b][cnt++] = c;
        }
    }
    g_nsel[b] = cnt;
}

// ---------------------------------------------------------------------------
// Kernel 2: per (batch, slot, n-tile) 128x128 SGEMM over K=D, fused epilogue:
//   out = (A@W + bias + PE(t, h)) * sqrt(CHUNK)   for live slots
//   out = 0                                        for slots >= n_unique
// A rows are the 128 rows of the selected chunk in `data`.
// Classic double-buffered SGEMM: BM=BN=128, BK=8, 256 threads, 8x8 microtile.
// ---------------------------------------------------------------------------
__global__ __launch_bounds__(256, 2)
void chunk_gemm_kernel(const float* __restrict__ data,
                       const float* __restrict__ W,
                       const float* __restrict__ bias,
                       float* __restrict__ out,
                       int D, int H, int T, int sample) {
    const int ntile = blockIdx.x;   // H / 128 tiles
    const int slot  = blockIdx.y;   // SAMPLE output slots
    const int b     = blockIdx.z;   // batch
    const int n0    = ntile * 128;
    const int Smax  = sample * CHUNK;
    const int tid   = threadIdx.x;

    float* outp = out + ((size_t)b * Smax + (size_t)slot * CHUNK) * H + n0;

    const int nsel = g_nsel[b];
    if (slot >= nsel) {
        // Zero-fill this 128x128 output tile (d_out is poisoned, must write).
        #pragma unroll 4
        for (int i = tid; i < 128 * 32; i += 256) {   // 32 float4 per row
            int r  = i >> 5;
            int c4 = (i & 31) * 4;
            *reinterpret_cast<float4*>(outp + (size_t)r * H + c4) =
                make_float4(0.f, 0.f, 0.f, 0.f);
        }
        return;
    }

    const int chunk = g_sel[b][slot];
    const float* A  = data + (size_t)b * T * D + (size_t)chunk * CHUNK * D;
    const float* Bw = W + n0;

    __shared__ float As[2][8][128];
    __shared__ float Bs[2][8][128];
    __shared__ float sdiv[64];

    // PE frequency table for this n-tile: div[i] = exp(2i * (-ln(1e4)/H)),
    // where column h = 2i (even -> sin, odd -> cos). Need i in [n0/2, n0/2+64).
    if (tid < 64) {
        int i = (n0 >> 1) + tid;
        sdiv[tid] = expf((float)(2 * i) * (-9.210340371976184f / (float)H));
    }

    // Global load mapping (one float4 of A and one of W per thread per K-tile)
    const int a_row = tid >> 1;          // 0..127
    const int a_col = (tid & 1) * 4;     // 0 or 4
    const int b_row = tid >> 5;          // 0..7
    const int b_col = (tid & 31) * 4;    // 0..124

    // Prologue: load K-tile 0
    {
        float4 av = *reinterpret_cast<const float4*>(A + (size_t)a_row * D + a_col);
        float4 bv = *reinterpret_cast<const float4*>(Bw + (size_t)b_row * H + b_col);
        As[0][a_col + 0][a_row] = av.x;
        As[0][a_col + 1][a_row] = av.y;
        As[0][a_col + 2][a_row] = av.z;
        As[0][a_col + 3][a_row] = av.w;
        *reinterpret_cast<float4*>(&Bs[0][b_row][b_col]) = bv;
    }
    __syncthreads();

    // Compute mapping: 16x16 thread grid, each thread owns an 8x8 microtile
    const int row_t = (tid >> 4) * 8;    // 0..120
    const int col_t = (tid & 15) * 8;    // 0..120

    float acc[8][8];
    #pragma unroll
    for (int i = 0; i < 8; ++i)
        #pragma unroll
        for (int j = 0; j < 8; ++j) acc[i][j] = 0.f;

    int buf = 0;
    for (int k0 = 0; k0 < D; k0 += 8) {
        const bool has_next = (k0 + 8) < D;
        float4 an, bn;
        if (has_next) {
            an = *reinterpret_cast<const float4*>(A + (size_t)a_row * D + (k0 + 8) + a_col);
            bn = *reinterpret_cast<const float4*>(Bw + (size_t)(k0 + 8 + b_row) * H + b_col);
        }

        #pragma unroll
        for (int k = 0; k < 8; ++k) {
            float ar[8], br[8];
            #pragma unroll
            for (int i = 0; i < 8; ++i) ar[i] = As[buf][k][row_t + i];
            #pragma unroll
            for (int j = 0; j < 8; ++j) br[j] = Bs[buf][k][col_t + j];
            #pragma unroll
            for (int i = 0; i < 8; ++i)
                #pragma unroll
                for (int j = 0; j < 8; ++j)
                    acc[i][j] = fmaf(ar[i], br[j], acc[i][j]);
        }

        if (has_next) {
            int nb = buf ^ 1;
            As[nb][a_col + 0][a_row] = an.x;
            As[nb][a_col + 1][a_row] = an.y;
            As[nb][a_col + 2][a_row] = an.z;
            As[nb][a_col + 3][a_row] = an.w;
            *reinterpret_cast<float4*>(&Bs[nb][b_row][b_col]) = bn;
            __syncthreads();
            buf = nb;
        }
    }

    // Epilogue: (acc + bias + PE(t, h)) * sqrt(CHUNK)
    const float scale = sqrtf((float)CHUNK);
    float bcol[8];
    #pragma unroll
    for (int j = 0; j < 8; ++j) bcol[j] = bias[n0 + col_t + j];

    float dv[4];
    #pragma unroll
    for (int jj = 0; jj < 4; ++jj) dv[jj] = sdiv[(col_t >> 1) + jj];

    #pragma unroll
    for (int i = 0; i < 8; ++i) {
        const float tpos = (float)(chunk * CHUNK + row_t + i);
        float v[8];
        #pragma unroll
        for (int jj = 0; jj < 4; ++jj) {
            float s, c;
            sincosf(tpos * dv[jj], &s, &c);
            const int j = jj * 2;
            v[j]     = (acc[i][j]     + bcol[j]     + s) * scale;
            v[j + 1] = (acc[i][j + 1] + bcol[j + 1] + c) * scale;
        }
        float4* op = reinterpret_cast<float4*>(outp + (size_t)(row_t + i) * H + col_t);
        op[0] = make_float4(v[0], v[1], v[2], v[3]);
        op[1] = make_float4(v[4], v[5], v[6], v[7]);
    }
}

// ---------------------------------------------------------------------------
// Launcher. Input order per metadata: state, data, W, b, chunk_idx.
// ---------------------------------------------------------------------------
extern "C" void kernel_launch(void* const* d_in, const int* in_sizes, int n_in,
                              void* d_out, int out_size) {
    const float* data      = (const float*)d_in[1];
    const float* W         = (const float*)d_in[2];
    const float* bias      = (const float*)d_in[3];
    const int*   chunk_idx = (const int*)d_in[4];
    float*       out       = (float*)d_out;

    const int H = in_sizes[3];                      // 1024
    const int D = in_sizes[2] / H;                  // 1024
    const int B = in_sizes[0] / (64 * H);           // state is (B, 64, H) -> 8
    const int T = in_sizes[1] / (B * D);            // 8192
    const int sample   = in_sizes[4] / B;           // 16
    const int n_chunks = T / CHUNK;                 // 64

    select_kernel<<<1, B>>>(chunk_idx, B, sample, n_chunks);

    dim3 grid(H / 128, sample, B);
    chunk_gemm_kernel<<<grid, 256>>>(data, W, bias, out, D, H, T, sample);
}

// round 7
// speedup vs baseline: 2.6840x; 2.6840x over previous
#include <cuda_runtime.h>
#include <math.h>
#include <stdint.h>

#define CHUNKT   128
#define MAXB     32
#define MAXSLOTS 64
#define BM       128
#define BN       128
#define BK       16
#define KSTRIDE  20      // smem row stride in floats (bank-conflict-free, 16B-aligned)

// Scratch (__device__ globals: no allocation allowed)
__device__ int   g_sel[MAXB][MAXSLOTS];
__device__ int   g_nsel[MAXB];
__device__ float g_WT[1024 * 1024];       // W^T, [H][D] K-major

// ---------------------------------------------------------------------------
// Kernel 1: sorted-unique chunk list per batch (= stable argsort of 1-mask)
// ---------------------------------------------------------------------------
__global__ void select_kernel(const int* __restrict__ chunk_idx,
                              int B, int sample, int n_chunks) {
    int b = blockIdx.x * blockDim.x + threadIdx.x;
    if (b >= B) return;
    unsigned long long mask = 0ull;
    for (int i = 0; i < sample; ++i) mask |= (1ull << chunk_idx[b * sample + i]);
    int cnt = 0;
    for (int c = 0; c < n_chunks; ++c)
        if ((mask >> c) & 1ull) g_sel[b][cnt++] = c;
    g_nsel[b] = cnt;
}

// ---------------------------------------------------------------------------
// Kernel 2: W[D,H] -> g_WT[H,D]
// ---------------------------------------------------------------------------
__global__ void transpose_kernel(const float* __restrict__ W, int D, int H) {
    __shared__ float tile[32][33];
    int h0 = blockIdx.x * 32, d0 = blockIdx.y * 32;
    int tx = threadIdx.x, ty = threadIdx.y;   // 32 x 8
    #pragma unroll
    for (int i = 0; i < 32; i += 8)
        tile[ty + i][tx] = W[(size_t)(d0 + ty + i) * H + h0 + tx];
    __syncthreads();
    #pragma unroll
    for (int i = 0; i < 32; i += 8)
        g_WT[(size_t)(h0 + ty + i) * D + d0 + tx] = tile[tx][ty + i];
}

// ---------------------------------------------------------------------------
// helpers
// ---------------------------------------------------------------------------
__device__ __forceinline__ uint32_t f2tf32(float x) {
    uint32_t r;
    asm("cvt.rna.tf32.f32 %0, %1;" : "=r"(r) : "f"(x));
    return r;
}

__device__ __forceinline__ void mma_tf32(float c[4], uint32_t a0, uint32_t a1,
                                         uint32_t a2, uint32_t a3,
                                         uint32_t b0, uint32_t b1) {
    asm volatile(
        "mma.sync.aligned.m16n8k8.row.col.f32.tf32.tf32.f32 "
        "{%0,%1,%2,%3}, {%4,%5,%6,%7}, {%8,%9}, {%0,%1,%2,%3};"
        : "+f"(c[0]), "+f"(c[1]), "+f"(c[2]), "+f"(c[3])
        : "r"(a0), "r"(a1), "r"(a2), "r"(a3), "r"(b0), "r"(b1));
}

// ---------------------------------------------------------------------------
// Kernel 3: tf32 mma.sync GEMM. One CTA = 128(M = one chunk) x 128(N), K = D.
// Double-buffered LDG -> cvt.tf32 -> STS.128 (R3-proven structure).
// 8 warps (2m x 4n), warp tile 64x32, 16 mma.m16n8k8 per k8 step.
// Epilogue fuses (+bias +PE(t,h)) * sqrt(128). Dead slots write zeros.
// ---------------------------------------------------------------------------
__global__ void __launch_bounds__(256, 2)
chunk_gemm_mma(const float* __restrict__ data,
               const float* __restrict__ bias,
               float* __restrict__ out,
               int D, int H, int T, int sample) {
    __shared__ uint32_t As[2][BM * KSTRIDE];
    __shared__ uint32_t Bs[2][BN * KSTRIDE];
    __shared__ float    s_div[BN / 2];
    __shared__ float    s_bias[BN];

    const int ntile = blockIdx.x;
    const int slot  = blockIdx.y;
    const int b     = blockIdx.z;
    const int n0    = ntile * BN;
    const int Smax  = sample * CHUNKT;
    const int tid   = threadIdx.x;
    const int wid   = tid >> 5;
    const int lane  = tid & 31;

    float* outp = out + ((size_t)b * Smax + (size_t)slot * CHUNKT) * H + n0;
    const int nsel = g_nsel[b];

    if (slot >= nsel) {                      // zero-fill 128 x 128 tile
        float4 z = make_float4(0.f, 0.f, 0.f, 0.f);
        #pragma unroll
        for (int i = 0; i < 16; ++i) {
            int idx = i * 256 + tid;
            int r = idx >> 5, c4 = (idx & 31) * 4;
            *reinterpret_cast<float4*>(outp + (size_t)r * H + c4) = z;
        }
        return;
    }

    const int chunk   = g_sel[b][slot];
    const float* Agm  = data + (size_t)b * T * D + (size_t)chunk * CHUNKT * D;
    const float* Bgm  = g_WT + (size_t)n0 * D;

    if (tid < BN / 2)
        s_div[tid] = __expf((float)(2 * ((n0 >> 1) + tid)) * (-9.210340371976184f / (float)H));
    if (tid < BN) s_bias[tid] = bias[n0 + tid];

    // Global staging map: thread -> 2 float4 of A and 2 of B per BK=16 chunk.
    // float4 i: row = tid/4 + i*64, k = (tid%4)*4.
    const int g_row = tid >> 2;
    const int g_k   = (tid & 3) * 4;

    // Warp tiling: wm in {0,1} (64 rows), wn in {0..3} (32 cols)
    const int wm = wid & 1;
    const int wn = wid >> 1;

    float acc[4][4][4];
    #pragma unroll
    for (int mt = 0; mt < 4; ++mt)
        #pragma unroll
        for (int nt = 0; nt < 4; ++nt)
            #pragma unroll
            for (int q = 0; q < 4; ++q) acc[mt][nt][q] = 0.f;

    const int NCHUNK = D / BK;               // 64

    // Prologue: stage + store chunk 0 into buffer 0
    {
        #pragma unroll
        for (int i = 0; i < 2; ++i) {
            int r = g_row + i * 64;
            float4 av = *reinterpret_cast<const float4*>(Agm + (size_t)r * D + g_k);
            float4 bv = *reinterpret_cast<const float4*>(Bgm + (size_t)r * D + g_k);
            uint32_t* ap = &As[0][r * KSTRIDE + g_k];
            uint32_t* bp = &Bs[0][r * KSTRIDE + g_k];
            ap[0] = f2tf32(av.x); ap[1] = f2tf32(av.y);
            ap[2] = f2tf32(av.z); ap[3] = f2tf32(av.w);
            bp[0] = f2tf32(bv.x); bp[1] = f2tf32(bv.y);
            bp[2] = f2tf32(bv.z); bp[3] = f2tf32(bv.w);
        }
    }
    __syncthreads();

    int buf = 0;
    for (int c = 0; c < NCHUNK; ++c) {
        const bool has_next = (c + 1) < NCHUNK;
        float4 an[2], bn[2];
        if (has_next) {
            const int k0 = (c + 1) * BK;
            #pragma unroll
            for (int i = 0; i < 2; ++i) {
                int r = g_row + i * 64;
                an[i] = *reinterpret_cast<const float4*>(Agm + (size_t)r * D + k0 + g_k);
                bn[i] = *reinterpret_cast<const float4*>(Bgm + (size_t)r * D + k0 + g_k);
            }
        }

        // Compute 2 k8 steps from smem[buf]
        const uint32_t* Ab = As[buf];
        const uint32_t* Bb = Bs[buf];
        #pragma unroll
        for (int k8 = 0; k8 < 2; ++k8) {
            const int kk = k8 * 8 + (lane & 3);
            uint32_t af[4][4], bf[4][2];
            #pragma unroll
            for (int mt = 0; mt < 4; ++mt) {
                const int mr = wm * 64 + mt * 16 + (lane >> 2);
                af[mt][0] = Ab[(mr)     * KSTRIDE + kk];
                af[mt][1] = Ab[(mr + 8) * KSTRIDE + kk];
                af[mt][2] = Ab[(mr)     * KSTRIDE + kk + 4];
                af[mt][3] = Ab[(mr + 8) * KSTRIDE + kk + 4];
            }
            #pragma unroll
            for (int nt = 0; nt < 4; ++nt) {
                const int nr = wn * 32 + nt * 8 + (lane >> 2);
                bf[nt][0] = Bb[nr * KSTRIDE + kk];
                bf[nt][1] = Bb[nr * KSTRIDE + kk + 4];
            }
            #pragma unroll
            for (int mt = 0; mt < 4; ++mt)
                #pragma unroll
                for (int nt = 0; nt < 4; ++nt)
                    mma_tf32(acc[mt][nt], af[mt][0], af[mt][1], af[mt][2], af[mt][3],
                             bf[nt][0], bf[nt][1]);
        }

        if (has_next) {
            const int nb = buf ^ 1;
            #pragma unroll
            for (int i = 0; i < 2; ++i) {
                int r = g_row + i * 64;
                uint32_t* ap = &As[nb][r * KSTRIDE + g_k];
                uint32_t* bp = &Bs[nb][r * KSTRIDE + g_k];
                ap[0] = f2tf32(an[i].x); ap[1] = f2tf32(an[i].y);
                ap[2] = f2tf32(an[i].z); ap[3] = f2tf32(an[i].w);
                bp[0] = f2tf32(bn[i].x); bp[1] = f2tf32(bn[i].y);
                bp[2] = f2tf32(bn[i].z); bp[3] = f2tf32(bn[i].w);
            }
            __syncthreads();
            buf = nb;
        }
    }

    // Epilogue: (acc + bias + PE(t,h)) * sqrt(128)
    const float scale = 11.313708498984761f;   // sqrt(128)
    const int   qrow  = lane >> 2;             // 0..7
    const int   qcol  = (lane & 3) * 2;        // 0,2,4,6

    #pragma unroll
    for (int mt = 0; mt < 4; ++mt) {
        #pragma unroll
        for (int nt = 0; nt < 4; ++nt) {
            const int col = wn * 32 + nt * 8 + qcol;     // even local col
            const float bs0 = s_bias[col], bs1 = s_bias[col + 1];
            const float dv  = s_div[col >> 1];
            #pragma unroll
            for (int h = 0; h < 2; ++h) {                // row halves (+0, +8)
                const int row = wm * 64 + mt * 16 + h * 8 + qrow;
                float s, cc;
                sincosf((float)(chunk * CHUNKT + row) * dv, &s, &cc);
                float2 v;
                v.x = (acc[mt][nt][h * 2 + 0] + bs0 + s)  * scale;
                v.y = (acc[mt][nt][h * 2 + 1] + bs1 + cc) * scale;
                *reinterpret_cast<float2*>(outp + (size_t)row * H + col) = v;
            }
        }
    }
}

// ---------------------------------------------------------------------------
// Launcher. Inputs: state, data, W, b, chunk_idx. Output float32.
// ---------------------------------------------------------------------------
extern "C" void kernel_launch(void* const* d_in, const int* in_sizes, int n_in,
                              void* d_out, int out_size) {
    const float* data      = (const float*)d_in[1];
    const float* W         = (const float*)d_in[2];
    const float* bias      = (const float*)d_in[3];
    const int*   chunk_idx = (const int*)d_in[4];
    float*       out       = (float*)d_out;

    const int H = in_sizes[3];                // 1024
    const int D = in_sizes[2] / H;            // 1024
    const int B = in_sizes[0] / (64 * H);     // 8
    const int T = in_sizes[1] / (B * D);      // 8192
    const int sample   = in_sizes[4] / B;     // 16
    const int n_chunks = T / CHUNKT;          // 64

    select_kernel<<<1, B>>>(chunk_idx, B, sample, n_chunks);
    transpose_kernel<<<dim3(H / 32, D / 32), dim3(32, 8)>>>(W, D, H);

    dim3 grid(H / BN, sample, B);
    chunk_gemm_mma<<<grid, 256>>>(data, bias, out, D, H, T, sample);
}

// round 8
// speedup vs baseline: 3.1230x; 1.1636x over previous
#include <cuda_runtime.h>
#include <math.h>
#include <stdint.h>

#define CHUNKT   128
#define MAXB     32
#define MAXSLOTS 64
#define BM       128
#define BN       128
#define BK       32
#define KSTR     36      // smem row stride in floats: 144B, 16B-aligned, conflict-free
#define MATB     (128 * KSTR * 4)          // bytes per matrix per stage (18432)
#define STAGEB   (2 * MATB)                // bytes per stage (A + B) = 36864
#define NSTAGE   3

// Scratch (__device__ globals: no allocation allowed)
__device__ int   g_sel[MAXB][MAXSLOTS];
__device__ int   g_nsel[MAXB];
__device__ float g_WT[1024 * 1024];       // W^T, [H][D] K-major

// ---------------------------------------------------------------------------
// Kernel 1: sorted-unique chunk list per batch (= stable argsort of 1-mask)
// ---------------------------------------------------------------------------
__global__ void select_kernel(const int* __restrict__ chunk_idx,
                              int B, int sample, int n_chunks) {
    int b = blockIdx.x * blockDim.x + threadIdx.x;
    if (b >= B) return;
    unsigned long long mask = 0ull;
    for (int i = 0; i < sample; ++i) mask |= (1ull << chunk_idx[b * sample + i]);
    int cnt = 0;
    for (int c = 0; c < n_chunks; ++c)
        if ((mask >> c) & 1ull) g_sel[b][cnt++] = c;
    g_nsel[b] = cnt;
}

// ---------------------------------------------------------------------------
// Kernel 2: W[D,H] -> g_WT[H,D]
// ---------------------------------------------------------------------------
__global__ void transpose_kernel(const float* __restrict__ W, int D, int H) {
    __shared__ float tile[32][33];
    int h0 = blockIdx.x * 32, d0 = blockIdx.y * 32;
    int tx = threadIdx.x, ty = threadIdx.y;   // 32 x 8
    #pragma unroll
    for (int i = 0; i < 32; i += 8)
        tile[ty + i][tx] = W[(size_t)(d0 + ty + i) * H + h0 + tx];
    __syncthreads();
    #pragma unroll
    for (int i = 0; i < 32; i += 8)
        g_WT[(size_t)(h0 + ty + i) * D + d0 + tx] = tile[tx][ty + i];
}

// ---------------------------------------------------------------------------
// helpers
// ---------------------------------------------------------------------------
__device__ __forceinline__ uint32_t cvta_shared(const void* p) {
    uint32_t a;
    asm("{ .reg .u64 t; cvta.to.shared.u64 t, %1; cvt.u32.u64 %0, t; }" : "=r"(a) : "l"(p));
    return a;
}
__device__ __forceinline__ void cp_async16(uint32_t dst, const void* src) {
    asm volatile("cp.async.cg.shared.global [%0], [%1], 16;" :: "r"(dst), "l"(src));
}
__device__ __forceinline__ uint32_t f2tf32(float x) {
    uint32_t r;
    asm("cvt.rna.tf32.f32 %0, %1;" : "=r"(r) : "f"(x));
    return r;
}
__device__ __forceinline__ void mma_tf32(float c[4], uint32_t a0, uint32_t a1,
                                         uint32_t a2, uint32_t a3,
                                         uint32_t b0, uint32_t b1) {
    asm volatile(
        "mma.sync.aligned.m16n8k8.row.col.f32.tf32.tf32.f32 "
        "{%0,%1,%2,%3}, {%4,%5,%6,%7}, {%8,%9}, {%0,%1,%2,%3};"
        : "+f"(c[0]), "+f"(c[1]), "+f"(c[2]), "+f"(c[3])
        : "r"(a0), "r"(a1), "r"(a2), "r"(a3), "r"(b0), "r"(b1));
}

// ---------------------------------------------------------------------------
// Kernel 3: tf32 mma.sync GEMM, cp.async pipelined.
// One CTA = 128(M = one chunk) x 128(N), K = D.
// 3 smem buffers, 2 loads in flight, BK=32 per stage, 1 syncthreads/iter.
// 8 warps (2m x 4n), warp tile 64x32. Epilogue fuses (+bias +PE)*sqrt(128).
// ---------------------------------------------------------------------------
__global__ void __launch_bounds__(256, 2)
chunk_gemm_mma(const float* __restrict__ data,
               const float* __restrict__ bias,
               float* __restrict__ out,
               int D, int H, int T, int sample) {
    extern __shared__ __align__(16) char smem[];
    __shared__ float s_div[BN / 2];
    __shared__ float s_bias[BN];

    const int ntile = blockIdx.x;
    const int slot  = blockIdx.y;
    const int b     = blockIdx.z;
    const int n0    = ntile * BN;
    const int Smax  = sample * CHUNKT;
    const int tid   = threadIdx.x;
    const int wid   = tid >> 5;
    const int lane  = tid & 31;

    float* outp = out + ((size_t)b * Smax + (size_t)slot * CHUNKT) * H + n0;
    const int nsel = g_nsel[b];

    if (slot >= nsel) {                      // zero-fill 128 x 128 tile
        float4 z = make_float4(0.f, 0.f, 0.f, 0.f);
        #pragma unroll
        for (int i = 0; i < 16; ++i) {
            int idx = i * 256 + tid;
            int r = idx >> 5, c4 = (idx & 31) * 4;
            *reinterpret_cast<float4*>(outp + (size_t)r * H + c4) = z;
        }
        return;
    }

    const int chunk   = g_sel[b][slot];
    const float* Agm  = data + (size_t)b * T * D + (size_t)chunk * CHUNKT * D;
    const float* Bgm  = g_WT + (size_t)n0 * D;

    if (tid < BN / 2)
        s_div[tid] = __expf((float)(2 * ((n0 >> 1) + tid)) * (-9.210340371976184f / (float)H));
    if (tid < BN) s_bias[tid] = bias[n0 + tid];

    const uint32_t sbase = cvta_shared(smem);

    // Per-thread cp.async map: 4 A-copies + 4 B-copies of 16B per stage.
    // idx = i*256 + tid; row = idx>>3 (0..127), kp = idx&7 (16B part of 128B row)
    const int cp_row = tid >> 3;             // base rows: +32 per i
    const int cp_kp  = tid & 7;

    // issue loads of K-chunk kc into stage buffer st
    auto load_stage = [&](int kc, int st) {
        const int k0 = kc * BK;
        const uint32_t abase = sbase + st * STAGEB;
        const uint32_t bbase = abase + MATB;
        #pragma unroll
        for (int i = 0; i < 4; ++i) {
            int r = cp_row + i * 32;
            cp_async16(abase + r * (KSTR * 4) + cp_kp * 16,
                       Agm + (size_t)r * D + k0 + cp_kp * 4);
        }
        #pragma unroll
        for (int i = 0; i < 4; ++i) {
            int r = cp_row + i * 32;
            cp_async16(bbase + r * (KSTR * 4) + cp_kp * 16,
                       Bgm + (size_t)r * D + k0 + cp_kp * 4);
        }
        asm volatile("cp.async.commit_group;" ::: "memory");
    };

    // Warp tiling: wm in {0,1} (64 rows), wn in {0..3} (32 cols)
    const int wm = wid & 1;
    const int wn = wid >> 1;

    float acc[4][4][4];
    #pragma unroll
    for (int mt = 0; mt < 4; ++mt)
        #pragma unroll
        for (int nt = 0; nt < 4; ++nt)
            #pragma unroll
            for (int q = 0; q < 4; ++q) acc[mt][nt][q] = 0.f;

    const int NCH = D / BK;                  // 32

    load_stage(0, 0);
    load_stage(1, 1);

    for (int c = 0; c < NCH; ++c) {
        asm volatile("cp.async.wait_group 1;" ::: "memory");
        __syncthreads();

        // prefetch chunk c+2 into the buffer freed at iteration c-1
        if (c + 2 < NCH) load_stage(c + 2, (c + 2) % NSTAGE);
        else             asm volatile("cp.async.commit_group;" ::: "memory");

        const float* Ab = reinterpret_cast<const float*>(smem + (c % NSTAGE) * STAGEB);
        const float* Bb = reinterpret_cast<const float*>(smem + (c % NSTAGE) * STAGEB + MATB);

        #pragma unroll
        for (int k8 = 0; k8 < 4; ++k8) {
            const int kk = k8 * 8 + (lane & 3);
            uint32_t af[4][4], bf[4][2];
            #pragma unroll
            for (int mt = 0; mt < 4; ++mt) {
                const int mr = wm * 64 + mt * 16 + (lane >> 2);
                af[mt][0] = f2tf32(Ab[(mr)     * KSTR + kk]);
                af[mt][1] = f2tf32(Ab[(mr + 8) * KSTR + kk]);
                af[mt][2] = f2tf32(Ab[(mr)     * KSTR + kk + 4]);
                af[mt][3] = f2tf32(Ab[(mr + 8) * KSTR + kk + 4]);
            }
            #pragma unroll
            for (int nt = 0; nt < 4; ++nt) {
                const int nr = wn * 32 + nt * 8 + (lane >> 2);
                bf[nt][0] = f2tf32(Bb[nr * KSTR + kk]);
                bf[nt][1] = f2tf32(Bb[nr * KSTR + kk + 4]);
            }
            #pragma unroll
            for (int mt = 0; mt < 4; ++mt)
                #pragma unroll
                for (int nt = 0; nt < 4; ++nt)
                    mma_tf32(acc[mt][nt], af[mt][0], af[mt][1], af[mt][2], af[mt][3],
                             bf[nt][0], bf[nt][1]);
        }
    }

    // Epilogue: (acc + bias + PE(t,h)) * sqrt(128)
    const float scale = 11.313708498984761f;   // sqrt(128)
    const int   qrow  = lane >> 2;             // 0..7
    const int   qcol  = (lane & 3) * 2;        // 0,2,4,6

    #pragma unroll
    for (int mt = 0; mt < 4; ++mt) {
        #pragma unroll
        for (int nt = 0; nt < 4; ++nt) {
            const int col = wn * 32 + nt * 8 + qcol;     // even local col
            const float bs0 = s_bias[col], bs1 = s_bias[col + 1];
            const float dv  = s_div[col >> 1];
            #pragma unroll
            for (int h = 0; h < 2; ++h) {                // row halves (+0, +8)
                const int row = wm * 64 + mt * 16 + h * 8 + qrow;
                float s, cc;
                __sincosf((float)(chunk * CHUNKT + row) * dv, &s, &cc);
                float2 v;
                v.x = (acc[mt][nt][h * 2 + 0] + bs0 + s)  * scale;
                v.y = (acc[mt][nt][h * 2 + 1] + bs1 + cc) * scale;
                *reinterpret_cast<float2*>(outp + (size_t)row * H + col) = v;
            }
        }
    }
}

// ---------------------------------------------------------------------------
// Launcher. Inputs: state, data, W, b, chunk_idx. Output float32.
// ---------------------------------------------------------------------------
extern "C" void kernel_launch(void* const* d_in, const int* in_sizes, int n_in,
                              void* d_out, int out_size) {
    const float* data      = (const float*)d_in[1];
    const float* W         = (const float*)d_in[2];
    const float* bias      = (const float*)d_in[3];
    const int*   chunk_idx = (const int*)d_in[4];
    float*       out       = (float*)d_out;

    const int H = in_sizes[3];                // 1024
    const int D = in_sizes[2] / H;            // 1024
    const int B = in_sizes[0] / (64 * H);     // 8
    const int T = in_sizes[1] / (B * D);      // 8192
    const int sample   = in_sizes[4] / B;     // 16
    const int n_chunks = T / CHUNKT;          // 64

    select_kernel<<<1, B>>>(chunk_idx, B, sample, n_chunks);
    transpose_kernel<<<dim3(H / 32, D / 32), dim3(32, 8)>>>(W, D, H);

    const int SMEM_BYTES = NSTAGE * STAGEB;   // 110592
    cudaFuncSetAttribute(chunk_gemm_mma,
                         cudaFuncAttributeMaxDynamicSharedMemorySize, SMEM_BYTES);
    dim3 grid(H / BN, sample, B);
    chunk_gemm_mma<<<grid, 256, SMEM_BYTES>>>(data, bias, out, D, H, T, sample);
}